// round 14
// baseline (speedup 1.0000x reference)
#include <cuda_runtime.h>
#include <math.h>

// Problem constants (shapes fixed by setup_inputs)
#define N_   131072
#define D_   64
#define K_   2048
#define RPB  128              // rows per block
#define CPC  256              // codes per smem chunk
#define NCH  (K_ / CPC)       // 8 chunks
#define XSS  132              // padded xs stride (floats)
#define TPB  256
#define GRID (N_ / RPB)       // 1024 blocks

typedef unsigned long long ull;

// Device scratch (no allocations allowed)
__device__ __align__(16) float g_en  [K_ * D_];   // normalized codebook [k][d]
__device__ __align__(16) float g_ent [K_ * D_];   // chunk-transposed: [chunk][d][c]
__device__ __align__(16) float g_see [K_];        // sum(en^2) per code
__device__ float g_part[GRID];                    // per-block loss partials
__device__ unsigned g_done;                       // zero-initialized; reset by last block

// ---- f32x2 helpers (FFMA2 is only reachable via PTX fma.rn.f32x2) ----
__device__ __forceinline__ ull dup2(float v) {
    ull r; asm("mov.b64 %0, {%1, %1};" : "=l"(r) : "r"(__float_as_uint(v))); return r;
}
__device__ __forceinline__ ull fma2(ull a, ull b, ull c) {
    ull d; asm("fma.rn.f32x2 %0, %1, %2, %3;" : "=l"(d) : "l"(a), "l"(b), "l"(c)); return d;
}
__device__ __forceinline__ void unpack2(ull v, float& lo, float& hi) {
    asm("mov.b64 {%0, %1}, %2;" : "=f"(lo), "=f"(hi) : "l"(v));
}
__device__ __forceinline__ void cp16(unsigned dst, const void* src) {
    asm volatile("cp.async.cg.shared.global [%0], [%1], 16;" :: "r"(dst), "l"(src) : "memory");
}
__device__ __forceinline__ void cp_commit() {
    asm volatile("cp.async.commit_group;" ::: "memory");
}
template<int W> __device__ __forceinline__ void cp_wait() {
    asm volatile("cp.async.wait_group %0;" :: "n"(W) : "memory");
}

// ---------------------------------------------------------------------------
// Kernel 1: normalize embeddings -> row-major + chunk-transposed + see[k].
// One warp per code row (D=64 -> 2 elems/lane).
// ---------------------------------------------------------------------------
__global__ void vq_norm_emb(const float* __restrict__ emb) {
    int w    = (blockIdx.x * blockDim.x + threadIdx.x) >> 5;   // code index
    int lane = threadIdx.x & 31;
    if (w >= K_) return;
    float v0 = emb[w * 64 + lane];
    float v1 = emb[w * 64 + lane + 32];
    float s  = v0 * v0 + v1 * v1;
    #pragma unroll
    for (int o = 16; o > 0; o >>= 1) s += __shfl_xor_sync(0xffffffffu, s, o);
    float inv = 1.0f / fmaxf(sqrtf(s), 1e-12f);
    float e0 = v0 * inv, e1 = v1 * inv;
    g_en[w * 64 + lane]      = e0;
    g_en[w * 64 + lane + 32] = e1;
    float t = e0 * e0 + e1 * e1;   // see from ROUNDED values (matches reference)
    #pragma unroll
    for (int o = 16; o > 0; o >>= 1) t += __shfl_xor_sync(0xffffffffu, t, o);
    if (lane == 0) g_see[w] = t;
    int ch = w >> 8, c = w & (CPC - 1);
    g_ent[(ch * 64 + lane)      * CPC + c] = e0;
    g_ent[(ch * 64 + lane + 32) * CPC + c] = e1;
}

// ---------------------------------------------------------------------------
// Kernel 2: fused normalize(x) + argmin + quantized_st + idx + loss,
// with the final loss reduction fused via last-block-done.
// Block: 128 rows x 2048 codes. Thread: 8 rows x 16 codes via f32x2 acc pairs.
// Double-buffered cp.async chunk loads (CPC=256 codes per chunk).
// ---------------------------------------------------------------------------
extern __shared__ float smem_[];

__global__ void __launch_bounds__(TPB, 1)
vq_main(const float* __restrict__ x, float* __restrict__ out, int out_size) {
    float* xs   = smem_;                          // [64][XSS]
    float* es0  = xs + 64 * XSS;                  // [64][CPC] buf 0
    float* es1  = es0 + 64 * CPC;                 // [64][CPC] buf 1
    float* sees = es1 + 64 * CPC;                 // [K_] all code see's

    int tid = threadIdx.x;
    int tx  = tid & 15;                  // code-pair group
    int ty  = tid >> 4;                  // row group (8 rows)
    int rowbase = blockIdx.x * RPB;

    unsigned es_u0 = (unsigned)__cvta_generic_to_shared(es0);
    unsigned es_u1 = (unsigned)__cvta_generic_to_shared(es1);

    // ---- prefetch chunk 0 (64KB) via cp.async ----
    {
        const float* src = g_ent;
        unsigned dst = es_u0 + (unsigned)tid * 16u;
        #pragma unroll
        for (int i = 0; i < 16; i++)
            cp16(dst + (unsigned)i * (TPB * 16u), src + (i * TPB + tid) * 4);
        cp_commit();
    }

    // ---- load all see's into smem (8KB) ----
    #pragma unroll
    for (int i = 0; i < 8; i++) sees[i * TPB + tid] = g_see[i * TPB + tid];

    // ---- load x tile, transposed ----
    #pragma unroll
    for (int i = 0; i < 32; i++) {
        int e = i * TPB + tid;
        int r = e >> 6, d = e & 63;
        xs[d * XSS + r] = x[(rowbase + r) * 64 + d];
    }
    __syncthreads();

    // ---- normalize rows (one thread per row) ----
    if (tid < RPB) {
        float s = 0.f;
        #pragma unroll
        for (int d = 0; d < 64; d++) { float v = xs[d * XSS + tid]; s += v * v; }
        float inv = 1.0f / fmaxf(sqrtf(s), 1e-12f);
        #pragma unroll
        for (int d = 0; d < 64; d++) xs[d * XSS + tid] *= inv;
    }
    // (sync before first compute happens inside the chunk loop)

    float minv[8], minkf[8], kf0[8];
    #pragma unroll
    for (int j = 0; j < 8; j++) { minv[j] = 3.4e38f; minkf[j] = 0.f; }
    #pragma unroll
    for (int p = 0; p < 8; p++) kf0[p] = (float)(2 * (tx + 16 * p));
    const ull M2 = dup2(-2.0f);
    float chbase = 0.f;

    for (int ch = 0; ch < NCH; ch++) {
        if (ch + 1 < NCH) {
            const float* src = g_ent + (ch + 1) * (64 * CPC);
            unsigned dst = (((ch + 1) & 1) ? es_u1 : es_u0) + (unsigned)tid * 16u;
            #pragma unroll
            for (int i = 0; i < 16; i++)
                cp16(dst + (unsigned)i * (TPB * 16u), src + (i * TPB + tid) * 4);
            cp_commit();
            cp_wait<1>();     // chunk ch has landed
        } else {
            cp_wait<0>();
        }
        __syncthreads();

        const ull* eb = (const ull*)((ch & 1) ? es1 : es0);

        ull acc[8][8];
        #pragma unroll
        for (int j = 0; j < 8; j++)
            #pragma unroll
            for (int p = 0; p < 8; p++) acc[j][p] = 0ull;

        #pragma unroll 4
        for (int d = 0; d < 64; d++) {
            float4 a0 = *(const float4*)(xs + d * XSS + ty * 8);
            float4 a1 = *(const float4*)(xs + d * XSS + ty * 8 + 4);
            ull A[8];
            A[0] = dup2(a0.x); A[1] = dup2(a0.y); A[2] = dup2(a0.z); A[3] = dup2(a0.w);
            A[4] = dup2(a1.x); A[5] = dup2(a1.y); A[6] = dup2(a1.z); A[7] = dup2(a1.w);
            ull B[8];
            #pragma unroll
            for (int p = 0; p < 8; p++) B[p] = eb[d * (CPC / 2) + tx + 16 * p];
            #pragma unroll
            for (int j = 0; j < 8; j++)
                #pragma unroll
                for (int p = 0; p < 8; p++)
                    acc[j][p] = fma2(A[j], B[p], acc[j][p]);
        }

        // argmin epilogue: compare v = see - 2*dot (sxx is row-constant)
        const ull* seeb = (const ull*)(sees + ch * CPC);
        #pragma unroll
        for (int p = 0; p < 8; p++) {
            ull S = seeb[tx + 16 * p];
            float klo = kf0[p] + chbase;
            #pragma unroll
            for (int j = 0; j < 8; j++) {
                ull v2 = fma2(M2, acc[j][p], S);
                float lo, hi; unpack2(v2, lo, hi);
                bool c1 = lo < minv[j];
                minv[j]  = c1 ? lo  : minv[j];
                minkf[j] = c1 ? klo : minkf[j];
                bool c2 = hi < minv[j];
                minv[j]  = c2 ? hi           : minv[j];
                minkf[j] = c2 ? (klo + 1.0f) : minkf[j];
            }
        }
        chbase += (float)CPC;
        __syncthreads();     // everyone done reading this buffer
    }

    // ---- reduce argmin across the 16 code-group threads per row ----
    float2* red = (float2*)es0;          // [RPB][16]
    #pragma unroll
    for (int j = 0; j < 8; j++)
        red[(ty * 8 + j) * 16 + tx] = make_float2(minv[j], minkf[j]);
    __syncthreads();

    float lsum = 0.f;
    if (tid < RPB) {
        float bv = 3.5e38f, bkf = 0.f;
        #pragma unroll
        for (int t = 0; t < 16; t++) {
            float2 e2 = red[tid * 16 + t];
            if (e2.x < bv || (e2.x == bv && e2.y < bkf)) { bv = e2.x; bkf = e2.y; }
        }
        int bk = (int)bkf;
        // reference re-normalizes the gathered code (idempotent, replicated)
        float inv2 = 1.0f / fmaxf(sqrtf(g_see[bk]), 1e-12f);
        const float* erow = g_en + bk * 64;
        #pragma unroll
        for (int d = 0; d < 64; d++) {
            float xnv  = xs[d * XSS + tid];
            float qd   = erow[d] * inv2;
            float diff = qd - xnv;
            lsum += diff * diff;
            xs[d * XSS + tid] = xnv + diff;      // quantized_st
        }
        if (out_size >= N_ * D_ + 1 + N_)
            out[N_ * D_ + 1 + rowbase + tid] = bkf;
    }
    __syncthreads();

    // ---- coalesced store of quantized_st tile ----
    #pragma unroll
    for (int i = 0; i < 32; i++) {
        int e = i * TPB + tid;
        out[rowbase * 64 + e] = xs[(e & 63) * XSS + (e >> 6)];
    }

    // ---- deterministic block loss reduction (reuse sees) ----
    if (tid < RPB) sees[tid] = lsum;
    __syncthreads();
    for (int s = 64; s > 0; s >>= 1) {
        if (tid < s) sees[tid] += sees[tid + s];
        __syncthreads();
    }
    if (tid == 0) g_part[blockIdx.x] = sees[0];

    // ---- fused final loss reduction: last block to finish does it ----
    __threadfence();                      // publish g_part + out writes
    __shared__ unsigned s_last;
    if (tid == 0) {
        unsigned t = atomicAdd(&g_done, 1u);
        s_last = (t == GRID - 1) ? 1u : 0u;
    }
    __syncthreads();
    if (s_last) {
        // identical tree to the old vq_final kernel (bit-for-bit)
        float s = g_part[tid] + g_part[tid + 256] + g_part[tid + 512] + g_part[tid + 768];
        sees[tid] = s;
        __syncthreads();
        for (int st = 128; st > 0; st >>= 1) {
            if (tid < st) sees[tid] += sees[tid + st];
            __syncthreads();
        }
        if (tid == 0) {
            if (out_size > N_ * D_)
                out[N_ * D_] = 1.25f * (sees[0] / (float)(N_ * D_));
            g_done = 0u;                  // reset for deterministic graph replay
        }
    }
}

// ---------------------------------------------------------------------------
extern "C" void kernel_launch(void* const* d_in, const int* in_sizes, int n_in,
                              void* d_out, int out_size) {
    const float* x;
    const float* emb;
    if (n_in >= 2 && in_sizes[0] >= in_sizes[1]) {
        x = (const float*)d_in[0]; emb = (const float*)d_in[1];
    } else {
        x = (const float*)d_in[1]; emb = (const float*)d_in[0];
    }

    const size_t dynsmem = (size_t)(64 * XSS + 2 * 64 * CPC + K_) * sizeof(float);
    cudaFuncSetAttribute(vq_main, cudaFuncAttributeMaxDynamicSharedMemorySize,
                         (int)dynsmem);

    vq_norm_emb<<<K_ / 8, 256>>>(emb);
    vq_main<<<GRID, TPB, dynsmem>>>(x, (float*)d_out, out_size);
}

// round 15
// speedup vs baseline: 1.0268x; 1.0268x over previous
#include <cuda_runtime.h>
#include <math.h>

// Problem constants (shapes fixed by setup_inputs)
#define N_   131072
#define D_   64
#define K_   2048
#define RPB  128              // rows per block
#define CPC  256              // codes per smem chunk
#define NCH  (K_ / CPC)       // 8 chunks
#define XSS  132              // padded xs stride (floats)
#define TPB  256
#define GRID (N_ / RPB)       // 1024 blocks

typedef unsigned long long ull;

// Device scratch (no allocations allowed)
__device__ __align__(16) float g_en  [K_ * D_];   // normalized codebook [k][d]
__device__ __align__(16) float g_ent [K_ * D_];   // chunk-transposed+interleaved (see below)
__device__ __align__(16) float g_see [K_];        // sum(en^2) per code
__device__ float g_part[GRID];                    // per-block loss partials

// B smem layout per d-row (128 u64 pairs): logical pair pi = tx*8 + p lives at
// u64 slot (p>>1)*32 + tx*2 + (p&1).  Thread tx then reads its 8 pairs with
// 4 conflict-free LDS.128 (16 lanes x consecutive 16B slots per instruction).

// ---- f32x2 helpers (FFMA2 is only reachable via PTX fma.rn.f32x2) ----
__device__ __forceinline__ ull dup2(float v) {
    ull r; asm("mov.b64 %0, {%1, %1};" : "=l"(r) : "r"(__float_as_uint(v))); return r;
}
__device__ __forceinline__ ull fma2(ull a, ull b, ull c) {
    ull d; asm("fma.rn.f32x2 %0, %1, %2, %3;" : "=l"(d) : "l"(a), "l"(b), "l"(c)); return d;
}
__device__ __forceinline__ void unpack2(ull v, float& lo, float& hi) {
    asm("mov.b64 {%0, %1}, %2;" : "=f"(lo), "=f"(hi) : "l"(v));
}
__device__ __forceinline__ void cp16(unsigned dst, const void* src) {
    asm volatile("cp.async.cg.shared.global [%0], [%1], 16;" :: "r"(dst), "l"(src) : "memory");
}
__device__ __forceinline__ void cp_commit() {
    asm volatile("cp.async.commit_group;" ::: "memory");
}
template<int W> __device__ __forceinline__ void cp_wait() {
    asm volatile("cp.async.wait_group %0;" :: "n"(W) : "memory");
}

// ---------------------------------------------------------------------------
// Kernel 1: normalize embeddings -> row-major + interleaved chunk layout + see.
// One warp per code row (D=64 -> 2 elems/lane).
// ---------------------------------------------------------------------------
__global__ void vq_norm_emb(const float* __restrict__ emb) {
    int w    = (blockIdx.x * blockDim.x + threadIdx.x) >> 5;   // code index
    int lane = threadIdx.x & 31;
    if (w >= K_) return;
    float v0 = emb[w * 64 + lane];
    float v1 = emb[w * 64 + lane + 32];
    float s  = v0 * v0 + v1 * v1;
    #pragma unroll
    for (int o = 16; o > 0; o >>= 1) s += __shfl_xor_sync(0xffffffffu, s, o);
    float inv = 1.0f / fmaxf(sqrtf(s), 1e-12f);
    float e0 = v0 * inv, e1 = v1 * inv;
    g_en[w * 64 + lane]      = e0;
    g_en[w * 64 + lane + 32] = e1;
    float t = e0 * e0 + e1 * e1;   // see from ROUNDED values (matches reference)
    #pragma unroll
    for (int o = 16; o > 0; o >>= 1) t += __shfl_xor_sync(0xffffffffu, t, o);
    if (lane == 0) g_see[w] = t;
    // interleaved chunk layout for LDS.128 B loads
    int ch = w >> 8, c = w & (CPC - 1);
    int pi = c >> 1, l = c & 1;
    int tx = pi >> 3, p = pi & 7;
    int fidx = ((p >> 1) * 32 + tx * 2 + (p & 1)) * 2 + l;
    g_ent[(ch * 64 + lane)      * CPC + fidx] = e0;
    g_ent[(ch * 64 + lane + 32) * CPC + fidx] = e1;
}

// ---------------------------------------------------------------------------
// Kernel 2: fused normalize(x) + argmin + quantized_st + idx + loss.
// Block: 128 rows x 2048 codes. Thread: 8 rows x 16 codes via f32x2 acc pairs.
// Double-buffered cp.async chunk loads (CPC=256 codes per chunk).
// ---------------------------------------------------------------------------
extern __shared__ float smem_[];

__global__ void __launch_bounds__(TPB, 1)
vq_main(const float* __restrict__ x, float* __restrict__ out, int out_size) {
    float* xs   = smem_;                          // [64][XSS]
    float* es0  = xs + 64 * XSS;                  // [64][CPC] buf 0
    float* es1  = es0 + 64 * CPC;                 // [64][CPC] buf 1
    float* sees = es1 + 64 * CPC;                 // [K_] all code see's

    int tid = threadIdx.x;
    int tx  = tid & 15;                  // code-pair group
    int ty  = tid >> 4;                  // row group (8 rows)
    int rowbase = blockIdx.x * RPB;

    unsigned es_u0 = (unsigned)__cvta_generic_to_shared(es0);
    unsigned es_u1 = (unsigned)__cvta_generic_to_shared(es1);

    // ---- prefetch chunk 0 (64KB) via cp.async ----
    {
        const float* src = g_ent;
        unsigned dst = es_u0 + (unsigned)tid * 16u;
        #pragma unroll
        for (int i = 0; i < 16; i++)
            cp16(dst + (unsigned)i * (TPB * 16u), src + (i * TPB + tid) * 4);
        cp_commit();
    }

    // ---- load all see's into smem (8KB) ----
    #pragma unroll
    for (int i = 0; i < 8; i++) sees[i * TPB + tid] = g_see[i * TPB + tid];

    // ---- load x tile, transposed ----
    #pragma unroll
    for (int i = 0; i < 32; i++) {
        int e = i * TPB + tid;
        int r = e >> 6, d = e & 63;
        xs[d * XSS + r] = x[(rowbase + r) * 64 + d];
    }
    __syncthreads();

    // ---- normalize rows (one thread per row) ----
    if (tid < RPB) {
        float s = 0.f;
        #pragma unroll
        for (int d = 0; d < 64; d++) { float v = xs[d * XSS + tid]; s += v * v; }
        float inv = 1.0f / fmaxf(sqrtf(s), 1e-12f);
        #pragma unroll
        for (int d = 0; d < 64; d++) xs[d * XSS + tid] *= inv;
    }
    // (sync before first compute happens inside the chunk loop)

    float minv[8], minkf[8], kf0[8];
    #pragma unroll
    for (int j = 0; j < 8; j++) { minv[j] = 3.4e38f; minkf[j] = 0.f; }
    #pragma unroll
    for (int p = 0; p < 8; p++) kf0[p] = (float)(2 * (tx * 8 + p));
    const ull M2 = dup2(-2.0f);
    float chbase = 0.f;

    for (int ch = 0; ch < NCH; ch++) {
        if (ch + 1 < NCH) {
            const float* src = g_ent + (ch + 1) * (64 * CPC);
            unsigned dst = (((ch + 1) & 1) ? es_u1 : es_u0) + (unsigned)tid * 16u;
            #pragma unroll
            for (int i = 0; i < 16; i++)
                cp16(dst + (unsigned)i * (TPB * 16u), src + (i * TPB + tid) * 4);
            cp_commit();
            cp_wait<1>();     // chunk ch has landed
        } else {
            cp_wait<0>();
        }
        __syncthreads();

        const ull* eb = (const ull*)((ch & 1) ? es1 : es0);

        ull acc[8][8];
        #pragma unroll
        for (int j = 0; j < 8; j++)
            #pragma unroll
            for (int p = 0; p < 8; p++) acc[j][p] = 0ull;

        #pragma unroll 4
        for (int d = 0; d < 64; d++) {
            float4 a0 = *(const float4*)(xs + d * XSS + ty * 8);
            float4 a1 = *(const float4*)(xs + d * XSS + ty * 8 + 4);
            ull A[8];
            A[0] = dup2(a0.x); A[1] = dup2(a0.y); A[2] = dup2(a0.z); A[3] = dup2(a0.w);
            A[4] = dup2(a1.x); A[5] = dup2(a1.y); A[6] = dup2(a1.z); A[7] = dup2(a1.w);
            ull B[8];
            #pragma unroll
            for (int i = 0; i < 4; i++) {           // 4x conflict-free LDS.128
                ulonglong2 v = *(const ulonglong2*)(eb + d * (CPC / 2) + i * 32 + tx * 2);
                B[2 * i]     = v.x;
                B[2 * i + 1] = v.y;
            }
            #pragma unroll
            for (int j = 0; j < 8; j++)
                #pragma unroll
                for (int p = 0; p < 8; p++)
                    acc[j][p] = fma2(A[j], B[p], acc[j][p]);
        }

        // argmin epilogue: compare v = see - 2*dot (sxx is row-constant)
        const ull* seeb = (const ull*)(sees + ch * CPC);
        #pragma unroll
        for (int p = 0; p < 8; p++) {
            ull S = seeb[tx * 8 + p];               // pair pi = tx*8+p
            float klo = kf0[p] + chbase;
            #pragma unroll
            for (int j = 0; j < 8; j++) {
                ull v2 = fma2(M2, acc[j][p], S);
                float lo, hi; unpack2(v2, lo, hi);
                bool c1 = lo < minv[j];
                minv[j]  = c1 ? lo  : minv[j];
                minkf[j] = c1 ? klo : minkf[j];
                bool c2 = hi < minv[j];
                minv[j]  = c2 ? hi           : minv[j];
                minkf[j] = c2 ? (klo + 1.0f) : minkf[j];
            }
        }
        chbase += (float)CPC;
        __syncthreads();     // everyone done reading this buffer
    }

    // ---- reduce argmin across the 16 code-group threads per row ----
    float2* red = (float2*)es0;          // [RPB][16]
    #pragma unroll
    for (int j = 0; j < 8; j++)
        red[(ty * 8 + j) * 16 + tx] = make_float2(minv[j], minkf[j]);
    __syncthreads();

    float lsum = 0.f;
    if (tid < RPB) {
        float bv = 3.5e38f, bkf = 0.f;
        #pragma unroll
        for (int t = 0; t < 16; t++) {
            float2 e2 = red[tid * 16 + t];
            if (e2.x < bv || (e2.x == bv && e2.y < bkf)) { bv = e2.x; bkf = e2.y; }
        }
        int bk = (int)bkf;
        // reference re-normalizes the gathered code (idempotent, replicated)
        float inv2 = 1.0f / fmaxf(sqrtf(g_see[bk]), 1e-12f);
        const float* erow = g_en + bk * 64;
        #pragma unroll
        for (int d = 0; d < 64; d++) {
            float xnv  = xs[d * XSS + tid];
            float qd   = erow[d] * inv2;
            float diff = qd - xnv;
            lsum += diff * diff;
            xs[d * XSS + tid] = xnv + diff;      // quantized_st
        }
        if (out_size >= N_ * D_ + 1 + N_)
            out[N_ * D_ + 1 + rowbase + tid] = bkf;
    }
    __syncthreads();

    // ---- coalesced store of quantized_st tile ----
    #pragma unroll
    for (int i = 0; i < 32; i++) {
        int e = i * TPB + tid;
        out[rowbase * 64 + e] = xs[(e & 63) * XSS + (e >> 6)];
    }

    // ---- deterministic block loss reduction (reuse sees) ----
    if (tid < RPB) sees[tid] = lsum;
    __syncthreads();
    for (int s = 64; s > 0; s >>= 1) {
        if (tid < s) sees[tid] += sees[tid + s];
        __syncthreads();
    }
    if (tid == 0) g_part[blockIdx.x] = sees[0];
}

// ---------------------------------------------------------------------------
// Kernel 3: deterministic final loss reduction.
// loss = q_latent + 0.25*e_latent = 1.25 * mean((q - xn)^2)
// ---------------------------------------------------------------------------
__global__ void vq_final(float* __restrict__ out, int out_size) {
    __shared__ float sm[256];
    int tid = threadIdx.x;
    float s = g_part[tid] + g_part[tid + 256] + g_part[tid + 512] + g_part[tid + 768];
    sm[tid] = s;
    __syncthreads();
    for (int st = 128; st > 0; st >>= 1) {
        if (tid < st) sm[tid] += sm[tid + st];
        __syncthreads();
    }
    if (tid == 0 && out_size > N_ * D_)
        out[N_ * D_] = 1.25f * (sm[0] / (float)(N_ * D_));
}

// ---------------------------------------------------------------------------
extern "C" void kernel_launch(void* const* d_in, const int* in_sizes, int n_in,
                              void* d_out, int out_size) {
    const float* x;
    const float* emb;
    if (n_in >= 2 && in_sizes[0] >= in_sizes[1]) {
        x = (const float*)d_in[0]; emb = (const float*)d_in[1];
    } else {
        x = (const float*)d_in[1]; emb = (const float*)d_in[0];
    }

    const size_t dynsmem = (size_t)(64 * XSS + 2 * 64 * CPC + K_) * sizeof(float);
    cudaFuncSetAttribute(vq_main, cudaFuncAttributeMaxDynamicSharedMemorySize,
                         (int)dynsmem);

    vq_norm_emb<<<K_ / 8, 256>>>(emb);
    vq_main<<<GRID, TPB, dynsmem>>>(x, (float*)d_out, out_size);
    vq_final<<<1, 256>>>((float*)d_out, out_size);
}

// round 16
// speedup vs baseline: 1.0601x; 1.0324x over previous
#include <cuda_runtime.h>
#include <math.h>

// Problem constants (shapes fixed by setup_inputs)
#define N_   131072
#define D_   64
#define K_   2048
#define RPB  128              // rows per block
#define CPC  256              // codes per smem chunk
#define NCH  (K_ / CPC)       // 8 chunks
#define XSS  132              // padded xs stride (floats)
#define TPB  256
#define GRID (N_ / RPB)       // 1024 blocks

typedef unsigned long long ull;

// Device scratch (no allocations allowed)
__device__ __align__(16) float g_en  [K_ * D_];   // normalized codebook [k][d]
__device__ __align__(16) float g_ent [K_ * D_];   // chunk-transposed: [chunk][d][c]
__device__ __align__(16) float g_see [K_];        // sum(en^2) per code
__device__ float g_part[GRID];                    // per-block loss partials

// ---- f32x2 helpers (FFMA2 is only reachable via PTX fma.rn.f32x2) ----
__device__ __forceinline__ ull dup2(float v) {
    ull r; asm("mov.b64 %0, {%1, %1};" : "=l"(r) : "r"(__float_as_uint(v))); return r;
}
__device__ __forceinline__ ull fma2(ull a, ull b, ull c) {
    ull d; asm("fma.rn.f32x2 %0, %1, %2, %3;" : "=l"(d) : "l"(a), "l"(b), "l"(c)); return d;
}
__device__ __forceinline__ void unpack2(ull v, float& lo, float& hi) {
    asm("mov.b64 {%0, %1}, %2;" : "=f"(lo), "=f"(hi) : "l"(v));
}
__device__ __forceinline__ void cp16(unsigned dst, const void* src) {
    asm volatile("cp.async.cg.shared.global [%0], [%1], 16;" :: "r"(dst), "l"(src) : "memory");
}
__device__ __forceinline__ void cp_commit() {
    asm volatile("cp.async.commit_group;" ::: "memory");
}
template<int W> __device__ __forceinline__ void cp_wait() {
    asm volatile("cp.async.wait_group %0;" :: "n"(W) : "memory");
}

// ---------------------------------------------------------------------------
// Kernel 1: normalize embeddings -> row-major + chunk-transposed + see[k].
// One warp per code row (D=64 -> 2 elems/lane).
// ---------------------------------------------------------------------------
__global__ void vq_norm_emb(const float* __restrict__ emb) {
    int w    = (blockIdx.x * blockDim.x + threadIdx.x) >> 5;   // code index
    int lane = threadIdx.x & 31;
    if (w >= K_) return;
    float v0 = emb[w * 64 + lane];
    float v1 = emb[w * 64 + lane + 32];
    float s  = v0 * v0 + v1 * v1;
    #pragma unroll
    for (int o = 16; o > 0; o >>= 1) s += __shfl_xor_sync(0xffffffffu, s, o);
    float inv = 1.0f / fmaxf(sqrtf(s), 1e-12f);
    float e0 = v0 * inv, e1 = v1 * inv;
    g_en[w * 64 + lane]      = e0;
    g_en[w * 64 + lane + 32] = e1;
    float t = e0 * e0 + e1 * e1;   // see from ROUNDED values (matches reference)
    #pragma unroll
    for (int o = 16; o > 0; o >>= 1) t += __shfl_xor_sync(0xffffffffu, t, o);
    if (lane == 0) g_see[w] = t;
    int ch = w >> 8, c = w & (CPC - 1);
    g_ent[(ch * 64 + lane)      * CPC + c] = e0;
    g_ent[(ch * 64 + lane + 32) * CPC + c] = e1;
}

// ---------------------------------------------------------------------------
// Kernel 2: fused normalize(x) + argmin + quantized_st + idx + loss.
// Block: 128 rows x 2048 codes. Thread: 8 rows x 16 codes via f32x2 acc pairs.
// Double-buffered cp.async chunk loads (CPC=256 codes per chunk).
// ---------------------------------------------------------------------------
extern __shared__ float smem_[];

__global__ void __launch_bounds__(TPB, 1)
vq_main(const float* __restrict__ x, float* __restrict__ out, int out_size) {
    float* xs   = smem_;                          // [64][XSS]
    float* es0  = xs + 64 * XSS;                  // [64][CPC] buf 0
    float* es1  = es0 + 64 * CPC;                 // [64][CPC] buf 1
    float* sees = es1 + 64 * CPC;                 // [K_] all code see's

    int tid = threadIdx.x;
    int tx  = tid & 15;                  // code-pair group
    int ty  = tid >> 4;                  // row group (8 rows)
    int rowbase = blockIdx.x * RPB;

    unsigned es_u0 = (unsigned)__cvta_generic_to_shared(es0);
    unsigned es_u1 = (unsigned)__cvta_generic_to_shared(es1);

    // ---- prefetch chunk 0 (64KB) via cp.async ----
    {
        const float* src = g_ent;
        unsigned dst = es_u0 + (unsigned)tid * 16u;
        #pragma unroll
        for (int i = 0; i < 16; i++)
            cp16(dst + (unsigned)i * (TPB * 16u), src + (i * TPB + tid) * 4);
        cp_commit();
    }

    // ---- load all see's into smem (8KB) ----
    #pragma unroll
    for (int i = 0; i < 8; i++) sees[i * TPB + tid] = g_see[i * TPB + tid];

    // ---- load x tile, transposed ----
    #pragma unroll
    for (int i = 0; i < 32; i++) {
        int e = i * TPB + tid;
        int r = e >> 6, d = e & 63;
        xs[d * XSS + r] = x[(rowbase + r) * 64 + d];
    }
    __syncthreads();

    // ---- normalize rows (one thread per row) ----
    if (tid < RPB) {
        float s = 0.f;
        #pragma unroll
        for (int d = 0; d < 64; d++) { float v = xs[d * XSS + tid]; s += v * v; }
        float inv = 1.0f / fmaxf(sqrtf(s), 1e-12f);
        #pragma unroll
        for (int d = 0; d < 64; d++) xs[d * XSS + tid] *= inv;
    }
    // (sync before first compute happens inside the chunk loop)

    float minv[8], minkf[8], kf0[8];
    #pragma unroll
    for (int j = 0; j < 8; j++) { minv[j] = 3.4e38f; minkf[j] = 0.f; }
    #pragma unroll
    for (int p = 0; p < 8; p++) kf0[p] = (float)(2 * (tx + 16 * p));
    const ull M2 = dup2(-2.0f);
    float chbase = 0.f;

    for (int ch = 0; ch < NCH; ch++) {
        if (ch + 1 < NCH) {
            const float* src = g_ent + (ch + 1) * (64 * CPC);
            unsigned dst = (((ch + 1) & 1) ? es_u1 : es_u0) + (unsigned)tid * 16u;
            #pragma unroll
            for (int i = 0; i < 16; i++)
                cp16(dst + (unsigned)i * (TPB * 16u), src + (i * TPB + tid) * 4);
            cp_commit();
            cp_wait<1>();     // chunk ch has landed
        } else {
            cp_wait<0>();
        }
        __syncthreads();

        const ull* eb = (const ull*)((ch & 1) ? es1 : es0);

        ull acc[8][8];
        #pragma unroll
        for (int j = 0; j < 8; j++)
            #pragma unroll
            for (int p = 0; p < 8; p++) acc[j][p] = 0ull;

        #pragma unroll 8
        for (int d = 0; d < 64; d++) {
            float4 a0 = *(const float4*)(xs + d * XSS + ty * 8);
            float4 a1 = *(const float4*)(xs + d * XSS + ty * 8 + 4);
            ull A[8];
            A[0] = dup2(a0.x); A[1] = dup2(a0.y); A[2] = dup2(a0.z); A[3] = dup2(a0.w);
            A[4] = dup2(a1.x); A[5] = dup2(a1.y); A[6] = dup2(a1.z); A[7] = dup2(a1.w);
            ull B[8];
            #pragma unroll
            for (int p = 0; p < 8; p++) B[p] = eb[d * (CPC / 2) + tx + 16 * p];
            #pragma unroll
            for (int j = 0; j < 8; j++)
                #pragma unroll
                for (int p = 0; p < 8; p++)
                    acc[j][p] = fma2(A[j], B[p], acc[j][p]);
        }

        // argmin epilogue: compare v = see - 2*dot (sxx is row-constant)
        const ull* seeb = (const ull*)(sees + ch * CPC);
        #pragma unroll
        for (int p = 0; p < 8; p++) {
            ull S = seeb[tx + 16 * p];
            float klo = kf0[p] + chbase;
            #pragma unroll
            for (int j = 0; j < 8; j++) {
                ull v2 = fma2(M2, acc[j][p], S);
                float lo, hi; unpack2(v2, lo, hi);
                // strictly-less update preserves first-index tie-break;
                // fminf + single select per value (FMNMX + FSEL)
                minkf[j] = (lo < minv[j]) ? klo : minkf[j];
                minv[j]  = fminf(lo, minv[j]);
                minkf[j] = (hi < minv[j]) ? (klo + 1.0f) : minkf[j];
                minv[j]  = fminf(hi, minv[j]);
            }
        }
        chbase += (float)CPC;
        __syncthreads();     // everyone done reading this buffer
    }

    // ---- reduce argmin across the 16 code-group threads per row ----
    float2* red = (float2*)es0;          // [RPB][16]
    #pragma unroll
    for (int j = 0; j < 8; j++)
        red[(ty * 8 + j) * 16 + tx] = make_float2(minv[j], minkf[j]);
    __syncthreads();

    float lsum = 0.f;
    if (tid < RPB) {
        float bv = 3.5e38f, bkf = 0.f;
        #pragma unroll
        for (int t = 0; t < 16; t++) {
            float2 e2 = red[tid * 16 + t];
            if (e2.x < bv || (e2.x == bv && e2.y < bkf)) { bv = e2.x; bkf = e2.y; }
        }
        int bk = (int)bkf;
        // reference re-normalizes the gathered code (idempotent, replicated)
        float inv2 = 1.0f / fmaxf(sqrtf(g_see[bk]), 1e-12f);
        const float* erow = g_en + bk * 64;
        #pragma unroll
        for (int d = 0; d < 64; d++) {
            float xnv  = xs[d * XSS + tid];
            float qd   = erow[d] * inv2;
            float diff = qd - xnv;
            lsum += diff * diff;
            xs[d * XSS + tid] = xnv + diff;      // quantized_st
        }
        if (out_size >= N_ * D_ + 1 + N_)
            out[N_ * D_ + 1 + rowbase + tid] = bkf;
    }
    __syncthreads();

    // ---- coalesced store of quantized_st tile ----
    #pragma unroll
    for (int i = 0; i < 32; i++) {
        int e = i * TPB + tid;
        out[rowbase * 64 + e] = xs[(e & 63) * XSS + (e >> 6)];
    }

    // ---- deterministic block loss reduction (reuse sees) ----
    if (tid < RPB) sees[tid] = lsum;
    __syncthreads();
    for (int s = 64; s > 0; s >>= 1) {
        if (tid < s) sees[tid] += sees[tid + s];
        __syncthreads();
    }
    if (tid == 0) g_part[blockIdx.x] = sees[0];
}

// ---------------------------------------------------------------------------
// Kernel 3: deterministic final loss reduction.
// loss = q_latent + 0.25*e_latent = 1.25 * mean((q - xn)^2)
// ---------------------------------------------------------------------------
__global__ void vq_final(float* __restrict__ out, int out_size) {
    __shared__ float sm[256];
    int tid = threadIdx.x;
    float s = g_part[tid] + g_part[tid + 256] + g_part[tid + 512] + g_part[tid + 768];
    sm[tid] = s;
    __syncthreads();
    for (int st = 128; st > 0; st >>= 1) {
        if (tid < st) sm[tid] += sm[tid + st];
        __syncthreads();
    }
    if (tid == 0 && out_size > N_ * D_)
        out[N_ * D_] = 1.25f * (sm[0] / (float)(N_ * D_));
}

// ---------------------------------------------------------------------------
extern "C" void kernel_launch(void* const* d_in, const int* in_sizes, int n_in,
                              void* d_out, int out_size) {
    const float* x;
    const float* emb;
    if (n_in >= 2 && in_sizes[0] >= in_sizes[1]) {
        x = (const float*)d_in[0]; emb = (const float*)d_in[1];
    } else {
        x = (const float*)d_in[1]; emb = (const float*)d_in[0];
    }

    const size_t dynsmem = (size_t)(64 * XSS + 2 * 64 * CPC + K_) * sizeof(float);
    cudaFuncSetAttribute(vq_main, cudaFuncAttributeMaxDynamicSharedMemorySize,
                         (int)dynsmem);

    vq_norm_emb<<<K_ / 8, 256>>>(emb);
    vq_main<<<GRID, TPB, dynsmem>>>(x, (float*)d_out, out_size);
    vq_final<<<1, 256>>>((float*)d_out, out_size);
}

// round 17
// speedup vs baseline: 1.0623x; 1.0021x over previous
#include <cuda_runtime.h>
#include <math.h>

// Problem constants (shapes fixed by setup_inputs)
#define N_   131072
#define D_   64
#define K_   2048
#define RPB  128              // rows per block
#define CPC  256              // codes per smem chunk
#define NCH  (K_ / CPC)       // 8 chunks
#define XSS  132              // padded xs stride (floats)
#define TPB  256
#define GRID (N_ / RPB)       // 1024 blocks

typedef unsigned long long ull;

// Device scratch (no allocations allowed)
__device__ __align__(16) float g_en  [K_ * D_];   // normalized codebook [k][d]
__device__ __align__(16) float g_ent [K_ * D_];   // chunk-transposed: [chunk][d][c]
__device__ __align__(16) float g_see [K_];        // sum(en^2) per code
__device__ float g_part[GRID];                    // per-block loss partials

// ---- f32x2 helpers (FFMA2 is only reachable via PTX fma.rn.f32x2) ----
__device__ __forceinline__ ull dup2(float v) {
    ull r; asm("mov.b64 %0, {%1, %1};" : "=l"(r) : "r"(__float_as_uint(v))); return r;
}
__device__ __forceinline__ ull fma2(ull a, ull b, ull c) {
    ull d; asm("fma.rn.f32x2 %0, %1, %2, %3;" : "=l"(d) : "l"(a), "l"(b), "l"(c)); return d;
}
__device__ __forceinline__ void unpack2(ull v, float& lo, float& hi) {
    asm("mov.b64 {%0, %1}, %2;" : "=f"(lo), "=f"(hi) : "l"(v));
}
__device__ __forceinline__ void cp16(unsigned dst, const void* src) {
    asm volatile("cp.async.cg.shared.global [%0], [%1], 16;" :: "r"(dst), "l"(src) : "memory");
}
__device__ __forceinline__ void cp_commit() {
    asm volatile("cp.async.commit_group;" ::: "memory");
}
template<int W> __device__ __forceinline__ void cp_wait() {
    asm volatile("cp.async.wait_group %0;" :: "n"(W) : "memory");
}

// ---------------------------------------------------------------------------
// Kernel 1: normalize embeddings -> row-major + chunk-transposed + see[k].
// One warp per code row (D=64 -> 2 elems/lane).
// ---------------------------------------------------------------------------
__global__ void vq_norm_emb(const float* __restrict__ emb) {
    int w    = (blockIdx.x * blockDim.x + threadIdx.x) >> 5;   // code index
    int lane = threadIdx.x & 31;
    if (w >= K_) return;
    float v0 = emb[w * 64 + lane];
    float v1 = emb[w * 64 + lane + 32];
    float s  = v0 * v0 + v1 * v1;
    #pragma unroll
    for (int o = 16; o > 0; o >>= 1) s += __shfl_xor_sync(0xffffffffu, s, o);
    float inv = 1.0f / fmaxf(sqrtf(s), 1e-12f);
    float e0 = v0 * inv, e1 = v1 * inv;
    g_en[w * 64 + lane]      = e0;
    g_en[w * 64 + lane + 32] = e1;
    float t = e0 * e0 + e1 * e1;   // see from ROUNDED values (matches reference)
    #pragma unroll
    for (int o = 16; o > 0; o >>= 1) t += __shfl_xor_sync(0xffffffffu, t, o);
    if (lane == 0) g_see[w] = t;
    int ch = w >> 8, c = w & (CPC - 1);
    g_ent[(ch * 64 + lane)      * CPC + c] = e0;
    g_ent[(ch * 64 + lane + 32) * CPC + c] = e1;
}

// ---------------------------------------------------------------------------
// Kernel 2: fused normalize(x) + argmin + quantized_st + idx + loss.
// Block: 128 rows x 2048 codes. Thread: 8 rows x 16 codes via f32x2 acc pairs.
// Double-buffered cp.async chunk loads (CPC=256 codes per chunk).
// ---------------------------------------------------------------------------
extern __shared__ float smem_[];

__global__ void __launch_bounds__(TPB, 1)
vq_main(const float* __restrict__ x, float* __restrict__ out, int out_size) {
    float* xs   = smem_;                          // [64][XSS]
    float* es0  = xs + 64 * XSS;                  // [64][CPC] buf 0
    float* es1  = es0 + 64 * CPC;                 // [64][CPC] buf 1
    float* sees = es1 + 64 * CPC;                 // [K_] all code see's

    int tid = threadIdx.x;
    int tx  = tid & 15;                  // code-pair group
    int ty  = tid >> 4;                  // row group (8 rows)
    int rowbase = blockIdx.x * RPB;

    unsigned es_u0 = (unsigned)__cvta_generic_to_shared(es0);
    unsigned es_u1 = (unsigned)__cvta_generic_to_shared(es1);

    // ---- prefetch chunk 0 (64KB) via cp.async ----
    {
        const float* src = g_ent;
        unsigned dst = es_u0 + (unsigned)tid * 16u;
        #pragma unroll
        for (int i = 0; i < 16; i++)
            cp16(dst + (unsigned)i * (TPB * 16u), src + (i * TPB + tid) * 4);
        cp_commit();
    }

    // ---- load all see's into smem (8KB) ----
    #pragma unroll
    for (int i = 0; i < 8; i++) sees[i * TPB + tid] = g_see[i * TPB + tid];

    // ---- load x tile, transposed ----
    #pragma unroll
    for (int i = 0; i < 32; i++) {
        int e = i * TPB + tid;
        int r = e >> 6, d = e & 63;
        xs[d * XSS + r] = x[(rowbase + r) * 64 + d];
    }
    __syncthreads();

    // ---- normalize rows (one thread per row) ----
    if (tid < RPB) {
        float s = 0.f;
        #pragma unroll
        for (int d = 0; d < 64; d++) { float v = xs[d * XSS + tid]; s += v * v; }
        float inv = 1.0f / fmaxf(sqrtf(s), 1e-12f);
        #pragma unroll
        for (int d = 0; d < 64; d++) xs[d * XSS + tid] *= inv;
    }
    // (sync before first compute happens inside the chunk loop)

    float minv[8], minkf[8], kf0[8];
    #pragma unroll
    for (int j = 0; j < 8; j++) { minv[j] = 3.4e38f; minkf[j] = 0.f; }
    #pragma unroll
    for (int p = 0; p < 8; p++) kf0[p] = (float)(2 * (tx + 16 * p));
    const ull M2 = dup2(-2.0f);
    float chbase = 0.f;

    for (int ch = 0; ch < NCH; ch++) {
        if (ch + 1 < NCH) {
            const float* src = g_ent + (ch + 1) * (64 * CPC);
            unsigned dst = (((ch + 1) & 1) ? es_u1 : es_u0) + (unsigned)tid * 16u;
            #pragma unroll
            for (int i = 0; i < 16; i++)
                cp16(dst + (unsigned)i * (TPB * 16u), src + (i * TPB + tid) * 4);
            cp_commit();
            cp_wait<1>();     // chunk ch has landed
        } else {
            cp_wait<0>();
        }
        __syncthreads();

        const ull* eb = (const ull*)((ch & 1) ? es1 : es0);

        ull acc[8][8];
        #pragma unroll
        for (int j = 0; j < 8; j++)
            #pragma unroll
            for (int p = 0; p < 8; p++) acc[j][p] = 0ull;

        #pragma unroll 16
        for (int d = 0; d < 64; d++) {
            float4 a0 = *(const float4*)(xs + d * XSS + ty * 8);
            float4 a1 = *(const float4*)(xs + d * XSS + ty * 8 + 4);
            ull A[8];
            A[0] = dup2(a0.x); A[1] = dup2(a0.y); A[2] = dup2(a0.z); A[3] = dup2(a0.w);
            A[4] = dup2(a1.x); A[5] = dup2(a1.y); A[6] = dup2(a1.z); A[7] = dup2(a1.w);
            ull B[8];
            #pragma unroll
            for (int p = 0; p < 8; p++) B[p] = eb[d * (CPC / 2) + tx + 16 * p];
            #pragma unroll
            for (int j = 0; j < 8; j++)
                #pragma unroll
                for (int p = 0; p < 8; p++)
                    acc[j][p] = fma2(A[j], B[p], acc[j][p]);
        }

        // argmin epilogue: compare v = see - 2*dot (sxx is row-constant)
        const ull* seeb = (const ull*)(sees + ch * CPC);
        #pragma unroll
        for (int p = 0; p < 8; p++) {
            ull S = seeb[tx + 16 * p];
            float klo = kf0[p] + chbase;
            #pragma unroll
            for (int j = 0; j < 8; j++) {
                ull v2 = fma2(M2, acc[j][p], S);
                float lo, hi; unpack2(v2, lo, hi);
                // strictly-less update preserves first-index tie-break;
                // fminf + single select per value (FMNMX + FSEL)
                minkf[j] = (lo < minv[j]) ? klo : minkf[j];
                minv[j]  = fminf(lo, minv[j]);
                minkf[j] = (hi < minv[j]) ? (klo + 1.0f) : minkf[j];
                minv[j]  = fminf(hi, minv[j]);
            }
        }
        chbase += (float)CPC;
        __syncthreads();     // everyone done reading this buffer
    }

    // ---- reduce argmin across the 16 code-group threads per row ----
    float2* red = (float2*)es0;          // [RPB][16]
    #pragma unroll
    for (int j = 0; j < 8; j++)
        red[(ty * 8 + j) * 16 + tx] = make_float2(minv[j], minkf[j]);
    __syncthreads();

    float lsum = 0.f;
    if (tid < RPB) {
        float bv = 3.5e38f, bkf = 0.f;
        #pragma unroll
        for (int t = 0; t < 16; t++) {
            float2 e2 = red[tid * 16 + t];
            if (e2.x < bv || (e2.x == bv && e2.y < bkf)) { bv = e2.x; bkf = e2.y; }
        }
        int bk = (int)bkf;
        // reference re-normalizes the gathered code (idempotent, replicated)
        float inv2 = 1.0f / fmaxf(sqrtf(g_see[bk]), 1e-12f);
        const float* erow = g_en + bk * 64;
        #pragma unroll
        for (int d = 0; d < 64; d++) {
            float xnv  = xs[d * XSS + tid];
            float qd   = erow[d] * inv2;
            float diff = qd - xnv;
            lsum += diff * diff;
            xs[d * XSS + tid] = xnv + diff;      // quantized_st
        }
        if (out_size >= N_ * D_ + 1 + N_)
            out[N_ * D_ + 1 + rowbase + tid] = bkf;
    }
    __syncthreads();

    // ---- coalesced store of quantized_st tile ----
    #pragma unroll
    for (int i = 0; i < 32; i++) {
        int e = i * TPB + tid;
        out[rowbase * 64 + e] = xs[(e & 63) * XSS + (e >> 6)];
    }

    // ---- deterministic block loss reduction (reuse sees) ----
    if (tid < RPB) sees[tid] = lsum;
    __syncthreads();
    for (int s = 64; s > 0; s >>= 1) {
        if (tid < s) sees[tid] += sees[tid + s];
        __syncthreads();
    }
    if (tid == 0) g_part[blockIdx.x] = sees[0];
}

// ---------------------------------------------------------------------------
// Kernel 3: deterministic final loss reduction.
// loss = q_latent + 0.25*e_latent = 1.25 * mean((q - xn)^2)
// ---------------------------------------------------------------------------
__global__ void vq_final(float* __restrict__ out, int out_size) {
    __shared__ float sm[256];
    int tid = threadIdx.x;
    float s = g_part[tid] + g_part[tid + 256] + g_part[tid + 512] + g_part[tid + 768];
    sm[tid] = s;
    __syncthreads();
    for (int st = 128; st > 0; st >>= 1) {
        if (tid < st) sm[tid] += sm[tid + st];
        __syncthreads();
    }
    if (tid == 0 && out_size > N_ * D_)
        out[N_ * D_] = 1.25f * (sm[0] / (float)(N_ * D_));
}

// ---------------------------------------------------------------------------
extern "C" void kernel_launch(void* const* d_in, const int* in_sizes, int n_in,
                              void* d_out, int out_size) {
    const float* x;
    const float* emb;
    if (n_in >= 2 && in_sizes[0] >= in_sizes[1]) {
        x = (const float*)d_in[0]; emb = (const float*)d_in[1];
    } else {
        x = (const float*)d_in[1]; emb = (const float*)d_in[0];
    }

    const size_t dynsmem = (size_t)(64 * XSS + 2 * 64 * CPC + K_) * sizeof(float);
    cudaFuncSetAttribute(vq_main, cudaFuncAttributeMaxDynamicSharedMemorySize,
                         (int)dynsmem);

    vq_norm_emb<<<K_ / 8, 256>>>(emb);
    vq_main<<<GRID, TPB, dynsmem>>>(x, (float*)d_out, out_size);
    vq_final<<<1, 256>>>((float*)d_out, out_size);
}